// round 2
// baseline (speedup 1.0000x reference)
#include <cuda_runtime.h>
#include <stdint.h>

#define NN 100000
#define DD 64
#define EE 1200000
#define AL 0.25f

// ---------------- scratch (static __device__, no allocs) ----------------
__device__ __align__(16) float g_deg[NN];
__device__ __align__(16) float g_dinv[NN];
__device__ __align__(16) float g_w[EE];
__device__ __align__(16) int   g_row0[EE];
__device__ __align__(16) int   g_col0[EE];
__device__ __align__(16) float g_normc[EE];
__device__ __align__(16) int   g_rowc[EE];
__device__ __align__(16) int   g_colc[EE];
__device__ int g_ne;
__device__ int g_idx_is32;   // 1 if edge_index stored as int32, 0 if int64
__device__ int g_mask_is8;   // 1 if mask stored as 1-byte, 0 if int32
__device__ __align__(16) float g_hbuf[2][NN * DD];

// ---------------- kernels ----------------

__global__ void k_reset() {
    g_ne = 0;
    g_idx_is32 = 0;
    g_mask_is8 = 0;
}

// Probe dtypes. eidx viewed as int32: reading [0, 2*EE) words is in-bounds for
// both int32 (2E words) and int64 (4E words) storage. For int64 (values < 2^31,
// nonneg) every odd word is 0; for int32 odd words are real node indices.
// mask viewed as bytes: reading [0, EE) bytes is in-bounds for both uint8 (E
// bytes) and int32 (4E bytes). For int32 bools, bytes at i%4!=0 are all 0.
__global__ void k_probe(const int* __restrict__ ei32,
                        const unsigned char* __restrict__ m8) {
    int any_odd = 0;
    for (long long i = (long long)blockIdx.x * blockDim.x + threadIdx.x;
         i < 2LL * EE; i += (long long)gridDim.x * blockDim.x) {
        if (i & 1) any_odd |= (ei32[i] != 0);
    }
    if (__syncthreads_or(any_odd)) {
        if (threadIdx.x == 0) g_idx_is32 = 1;
    }
    int any_off = 0;
    for (long long i = (long long)blockIdx.x * blockDim.x + threadIdx.x;
         i < (long long)EE; i += (long long)gridDim.x * blockDim.x) {
        if (i & 3) any_off |= (m8[i] != 0);
    }
    if (__syncthreads_or(any_off)) {
        if (threadIdx.x == 0) g_mask_is8 = 1;
    }
}

__global__ void k_zero4(float* __restrict__ p, int n4) {
    int i = blockIdx.x * blockDim.x + threadIdx.x;
    if (i < n4) reinterpret_cast<float4*>(p)[i] = make_float4(0.f, 0.f, 0.f, 0.f);
}

// per-edge: w = attr*mask, decode indices per dtype flags, accumulate degree
__global__ void k_prep(const float* __restrict__ attr,
                       const int* __restrict__ ei32,
                       const unsigned char* __restrict__ m8) {
    int e = blockIdx.x * blockDim.x + threadIdx.x;
    if (e >= EE) return;
    bool mk;
    if (g_mask_is8) {
        mk = (m8[e] != 0);
    } else {
        mk = (reinterpret_cast<const int*>(m8)[e] != 0);
    }
    int r, c;
    if (g_idx_is32) {
        r = ei32[e];
        c = ei32[EE + e];
    } else {
        r = ei32[2LL * e];
        c = ei32[2LL * (EE + e)];
    }
    float w = mk ? __ldg(attr + e) : 0.f;
    // clamp defensively (garbage indices would crash the whole bench)
    if ((unsigned)r >= NN || (unsigned)c >= NN) w = 0.f;
    g_w[e] = w;
    g_row0[e] = r;
    g_col0[e] = c;
    if (w > 0.f) atomicAdd(&g_deg[c], w);
}

__global__ void k_dinv() {
    int i = blockIdx.x * blockDim.x + threadIdx.x;
    if (i < NN) {
        float d = g_deg[i];
        g_dinv[i] = (d > 0.f) ? rsqrtf(d) : 0.f;
    }
}

// compute norm, compact nonzero edges (warp-aggregated atomic offsets)
__global__ void k_compact() {
    int e = blockIdx.x * blockDim.x + threadIdx.x;
    bool keep = false;
    float nr = 0.f;
    int r = 0, c = 0;
    if (e < EE) {
        float w = g_w[e];
        if (w > 0.f) {
            r = g_row0[e];
            c = g_col0[e];
            nr = w * g_dinv[r] * g_dinv[c];
            keep = (nr != 0.f);
        }
    }
    unsigned m = __ballot_sync(0xffffffffu, keep);
    if (!keep) return;
    int lane = threadIdx.x & 31;
    int leader = __ffs(m) - 1;
    int rank = __popc(m & ((1u << lane) - 1u));
    int base;
    if (lane == leader) base = atomicAdd(&g_ne, __popc(m));
    base = __shfl_sync(m, base, leader);
    int p = base + rank;
    g_normc[p] = nr;
    g_rowc[p] = r;
    g_colc[p] = c;
}

// scatter one layer: 16 threads per edge, float4 gather + vector red.add
__global__ void k_scatter(const float* __restrict__ hin, float* __restrict__ hout) {
    long long gid = (long long)blockIdx.x * blockDim.x + threadIdx.x;
    int e = (int)(gid >> 4);
    if (e >= g_ne) return;
    int lane = (int)(gid & 15);
    float nrm = g_normc[e];
    int r = g_rowc[e];
    int c = g_colc[e];
    float4 v = __ldg(reinterpret_cast<const float4*>(hin + (size_t)r * DD) + lane);
    v.x *= nrm; v.y *= nrm; v.z *= nrm; v.w *= nrm;
    float* dst = hout + (size_t)c * DD + lane * 4;
    asm volatile("red.global.add.v4.f32 [%0], {%1,%2,%3,%4};"
                 :: "l"(dst), "f"(v.x), "f"(v.y), "f"(v.z), "f"(v.w)
                 : "memory");
}

__global__ void k_init_out(float* __restrict__ out, const float* __restrict__ x) {
    int i = blockIdx.x * blockDim.x + threadIdx.x;
    if (i < NN * DD / 4) {
        float4 v = reinterpret_cast<const float4*>(x)[i];
        v.x *= AL; v.y *= AL; v.z *= AL; v.w *= AL;
        reinterpret_cast<float4*>(out)[i] = v;
    }
}

__global__ void k_axpy(float* __restrict__ out, const float* __restrict__ h) {
    int i = blockIdx.x * blockDim.x + threadIdx.x;
    if (i < NN * DD / 4) {
        float4 o = reinterpret_cast<float4*>(out)[i];
        float4 v = reinterpret_cast<const float4*>(h)[i];
        o.x += AL * v.x; o.y += AL * v.y; o.z += AL * v.z; o.w += AL * v.w;
        reinterpret_cast<float4*>(out)[i] = o;
    }
}

// ---------------- launch ----------------
extern "C" void kernel_launch(void* const* d_in, const int* in_sizes, int n_in,
                              void* d_out, int out_size) {
    const float* x = (const float*)d_in[0];
    const float* attr = (const float*)d_in[1];
    const int* ei32 = (const int*)d_in[2];
    const unsigned char* m8 = (const unsigned char*)d_in[3];
    float* out = (float*)d_out;

    void* hbp = nullptr;
    cudaGetSymbolAddress(&hbp, g_hbuf);
    float* h0 = (float*)hbp;
    float* h1 = h0 + (size_t)NN * DD;
    void* degp = nullptr;
    cudaGetSymbolAddress(&degp, g_deg);

    const int B = 256;
    const int nodes4 = NN * DD / 4;            // 1.6M float4
    const int gridNodes4 = (nodes4 + B - 1) / B;
    const int gridE = (EE + B - 1) / B;
    const int gridDeg = (NN / 4 + B - 1) / B;
    const int gridN = (NN + B - 1) / B;
    const long long sthreads = (long long)EE * 16;
    const int gridScatter = (int)((sthreads + B - 1) / B);

    // dtype probe + degree/norm precompute
    k_reset<<<1, 1>>>();
    k_probe<<<592, B>>>(ei32, m8);
    k_zero4<<<gridDeg, B>>>((float*)degp, NN / 4);
    k_prep<<<gridE, B>>>(attr, ei32, m8);
    k_dinv<<<gridN, B>>>();
    k_compact<<<gridE, B>>>();

    // out = alpha * x
    k_init_out<<<gridNodes4, B>>>(out, x);

    // layer 1: x -> h0
    k_zero4<<<gridNodes4, B>>>(h0, nodes4);
    k_scatter<<<gridScatter, B>>>(x, h0);
    k_axpy<<<gridNodes4, B>>>(out, h0);

    // layer 2: h0 -> h1
    k_zero4<<<gridNodes4, B>>>(h1, nodes4);
    k_scatter<<<gridScatter, B>>>(h0, h1);
    k_axpy<<<gridNodes4, B>>>(out, h1);

    // layer 3: h1 -> h0
    k_zero4<<<gridNodes4, B>>>(h0, nodes4);
    k_scatter<<<gridScatter, B>>>(h1, h0);
    k_axpy<<<gridNodes4, B>>>(out, h0);
}

// round 3
// speedup vs baseline: 1.9036x; 1.9036x over previous
#include <cuda_runtime.h>
#include <stdint.h>

#define NN 100000
#define DD 64
#define EE 1200000
#define AL 0.25f
#define SCAN_B 1024
#define NBLK ((NN + SCAN_B - 1) / SCAN_B)   // 98

// ---------------- scratch (static __device__, no allocs) ----------------
__device__ __align__(16) float g_deg[NN];
__device__ __align__(16) float g_dinv[NN];
__device__ __align__(16) float g_w[EE];
__device__ __align__(16) int   g_row0[EE];
__device__ __align__(16) int   g_col0[EE];
__device__ __align__(16) int2  g_pair[EE];      // (row, norm-as-int) grouped by col
__device__ __align__(16) int   g_cnt[NN];
__device__ __align__(16) int   g_off[NN + 1];
__device__ __align__(16) int   g_cur[NN];
__device__ int g_bsum[NBLK];
__device__ int g_bsum_off[NBLK];
__device__ int g_idx_is32;
__device__ int g_mask_is8;
__device__ __align__(16) float g_hbuf[3][NN * DD];

// ---------------- kernels ----------------

// zero deg (float), cnt (int), reset probe flags
__global__ void k_zero_misc() {
    int i = blockIdx.x * blockDim.x + threadIdx.x;
    if (i == 0) { g_idx_is32 = 0; g_mask_is8 = 0; }
    if (i < NN) { g_deg[i] = 0.f; g_cnt[i] = 0; }
}

// dtype probe (in-bounds under either int32/int64 and byte/int32-bool storage)
__global__ void k_probe(const int* __restrict__ ei32,
                        const unsigned char* __restrict__ m8) {
    int any_odd = 0;
    for (long long i = (long long)blockIdx.x * blockDim.x + threadIdx.x;
         i < 2LL * EE; i += (long long)gridDim.x * blockDim.x) {
        if (i & 1) any_odd |= (ei32[i] != 0);
    }
    if (__syncthreads_or(any_odd)) {
        if (threadIdx.x == 0) g_idx_is32 = 1;
    }
    int any_off = 0;
    for (long long i = (long long)blockIdx.x * blockDim.x + threadIdx.x;
         i < (long long)EE; i += (long long)gridDim.x * blockDim.x) {
        if (i & 3) any_off |= (m8[i] != 0);
    }
    if (__syncthreads_or(any_off)) {
        if (threadIdx.x == 0) g_mask_is8 = 1;
    }
}

// decode per dtype flags, w = attr*mask, accumulate weighted degree at col
__global__ void k_prep(const float* __restrict__ attr,
                       const int* __restrict__ ei32,
                       const unsigned char* __restrict__ m8) {
    int e = blockIdx.x * blockDim.x + threadIdx.x;
    if (e >= EE) return;
    bool mk = g_mask_is8 ? (m8[e] != 0)
                         : (reinterpret_cast<const int*>(m8)[e] != 0);
    int r, c;
    if (g_idx_is32) { r = ei32[e];        c = ei32[EE + e]; }
    else            { r = ei32[2LL * e];  c = ei32[2LL * (EE + e)]; }
    float w = mk ? __ldg(attr + e) : 0.f;
    if ((unsigned)r >= NN || (unsigned)c >= NN) w = 0.f;
    g_w[e] = w;
    g_row0[e] = r;
    g_col0[e] = c;
    if (w > 0.f) atomicAdd(&g_deg[c], w);
}

__global__ void k_dinv() {
    int i = blockIdx.x * blockDim.x + threadIdx.x;
    if (i < NN) {
        float d = g_deg[i];
        g_dinv[i] = (d > 0.f) ? rsqrtf(d) : 0.f;
    }
}

// count kept edges per target node (kept: w>0 and dinv[row]>0)
__global__ void k_count() {
    int e = blockIdx.x * blockDim.x + threadIdx.x;
    if (e >= EE) return;
    float w = g_w[e];
    if (w <= 0.f) return;
    if (g_dinv[g_row0[e]] == 0.f) return;
    atomicAdd(&g_cnt[g_col0[e]], 1);
}

// block-level exclusive scan of cnt
__global__ void k_scan1() {
    __shared__ int sm[SCAN_B];
    int i = blockIdx.x * SCAN_B + threadIdx.x;
    int v = (i < NN) ? g_cnt[i] : 0;
    sm[threadIdx.x] = v;
    __syncthreads();
    for (int d = 1; d < SCAN_B; d <<= 1) {
        int t = (threadIdx.x >= d) ? sm[threadIdx.x - d] : 0;
        __syncthreads();
        sm[threadIdx.x] += t;
        __syncthreads();
    }
    if (i < NN) g_off[i] = sm[threadIdx.x] - v;  // exclusive within block
    if (threadIdx.x == SCAN_B - 1) g_bsum[blockIdx.x] = sm[SCAN_B - 1];
}

// scan block sums (tiny, single thread)
__global__ void k_scan2() {
    int run = 0;
    for (int b = 0; b < NBLK; b++) {
        g_bsum_off[b] = run;
        run += g_bsum[b];
    }
    g_off[NN] = run;  // total kept edges
}

// add block offsets; init cursors
__global__ void k_scan3() {
    int i = blockIdx.x * blockDim.x + threadIdx.x;
    if (i < NN) {
        int o = g_off[i] + g_bsum_off[i / SCAN_B];
        g_off[i] = o;
        g_cur[i] = o;
    }
}

// fill CSR: (row, norm) pairs grouped by target col
__global__ void k_fill() {
    int e = blockIdx.x * blockDim.x + threadIdx.x;
    if (e >= EE) return;
    float w = g_w[e];
    if (w <= 0.f) return;
    int r = g_row0[e];
    float dr = g_dinv[r];
    if (dr == 0.f) return;
    int c = g_col0[e];
    float nrm = w * dr * g_dinv[c];
    int pos = atomicAdd(&g_cur[c], 1);
    g_pair[pos] = make_int2(r, __float_as_int(nrm));
}

// pull one layer: 16 threads per node, register accumulation, no atomics
__global__ void k_gather(const float* __restrict__ hin, float* __restrict__ hout) {
    int gid = blockIdx.x * blockDim.x + threadIdx.x;
    int node = gid >> 4;
    if (node >= NN) return;
    int lane = gid & 15;
    int beg = g_off[node];
    int end = g_off[node + 1];
    float4 acc = make_float4(0.f, 0.f, 0.f, 0.f);
    for (int j = beg; j < end; j++) {
        int2 pr = __ldg(&g_pair[j]);         // uniform across halfwarp -> broadcast
        float nrm = __int_as_float(pr.y);
        float4 v = __ldg(reinterpret_cast<const float4*>(hin + (size_t)pr.x * DD) + lane);
        acc.x = fmaf(nrm, v.x, acc.x);
        acc.y = fmaf(nrm, v.y, acc.y);
        acc.z = fmaf(nrm, v.z, acc.z);
        acc.w = fmaf(nrm, v.w, acc.w);
    }
    reinterpret_cast<float4*>(hout + (size_t)node * DD)[lane] = acc;
}

// out = AL * (x + h1 + h2 + h3)
__global__ void k_final(float* __restrict__ out, const float* __restrict__ x,
                        const float* __restrict__ h1, const float* __restrict__ h2,
                        const float* __restrict__ h3) {
    int i = blockIdx.x * blockDim.x + threadIdx.x;
    if (i < NN * DD / 4) {
        float4 a = reinterpret_cast<const float4*>(x)[i];
        float4 b = reinterpret_cast<const float4*>(h1)[i];
        float4 c = reinterpret_cast<const float4*>(h2)[i];
        float4 d = reinterpret_cast<const float4*>(h3)[i];
        float4 o;
        o.x = AL * (a.x + b.x + c.x + d.x);
        o.y = AL * (a.y + b.y + c.y + d.y);
        o.z = AL * (a.z + b.z + c.z + d.z);
        o.w = AL * (a.w + b.w + c.w + d.w);
        reinterpret_cast<float4*>(out)[i] = o;
    }
}

// ---------------- launch ----------------
extern "C" void kernel_launch(void* const* d_in, const int* in_sizes, int n_in,
                              void* d_out, int out_size) {
    const float* x = (const float*)d_in[0];
    const float* attr = (const float*)d_in[1];
    const int* ei32 = (const int*)d_in[2];
    const unsigned char* m8 = (const unsigned char*)d_in[3];
    float* out = (float*)d_out;

    void* hbp = nullptr;
    cudaGetSymbolAddress(&hbp, g_hbuf);
    float* h1 = (float*)hbp;
    float* h2 = h1 + (size_t)NN * DD;
    float* h3 = h2 + (size_t)NN * DD;

    const int B = 256;
    const int nodes4 = NN * DD / 4;
    const int gridNodes4 = (nodes4 + B - 1) / B;
    const int gridE = (EE + B - 1) / B;
    const int gridN = (NN + B - 1) / B;
    const int gridGather = (NN * 16 + B - 1) / B;

    k_zero_misc<<<gridN, B>>>();
    k_probe<<<592, B>>>(ei32, m8);
    k_prep<<<gridE, B>>>(attr, ei32, m8);
    k_dinv<<<gridN, B>>>();
    k_count<<<gridE, B>>>();
    k_scan1<<<NBLK, SCAN_B>>>();
    k_scan2<<<1, 1>>>();
    k_scan3<<<gridN, B>>>();
    k_fill<<<gridE, B>>>();

    k_gather<<<gridGather, B>>>(x,  h1);
    k_gather<<<gridGather, B>>>(h1, h2);
    k_gather<<<gridGather, B>>>(h2, h3);
    k_final<<<gridNodes4, B>>>(out, x, h1, h2, h3);
}

// round 4
// speedup vs baseline: 2.1686x; 1.1392x over previous
#include <cuda_runtime.h>
#include <stdint.h>

#define NN 100000
#define DD 64
#define EE 1200000
#define AL 0.25f
#define SCAN_B 1024
#define NBLK ((NN + SCAN_B - 1) / SCAN_B)   // 98

// ---------------- scratch (static __device__, no allocs) ----------------
__device__ __align__(16) float g_deg[NN];
__device__ __align__(16) float g_dinv[NN];
__device__ __align__(16) float g_w[EE];
__device__ __align__(16) int   g_row0[EE];
__device__ __align__(16) int   g_col0[EE];
__device__ __align__(16) int2  g_pair[EE];   // (row, norm bits) grouped by target col
__device__ __align__(16) int   g_cnt[NN];
__device__ __align__(16) int   g_off[NN + 1];
__device__ __align__(16) int   g_cur[NN];
__device__ int g_bsum[NBLK];
__device__ int g_bsum_off[NBLK];
__device__ int g_idx_is32;
__device__ int g_mask_is8;
__device__ __align__(16) float g_hbuf[2][NN * DD];

// ---------------- kernels ----------------

// zero deg/cnt; block 0 additionally does a sampled dtype probe.
// eidx viewed as int32: for int64 storage (values < 2^31) every odd word is 0;
// for int32 storage odd words are node indices (P(==0) = 1e-5 each).
// mask viewed as bytes: for int32-bool storage bytes at i%4!=0 are 0; for
// uint8 ~50% are nonzero. 16K samples -> detection is certain for real data;
// all reads are in-bounds under either interpretation.
__global__ void k_zero_probe(const int* __restrict__ ei32,
                             const unsigned char* __restrict__ m8) {
    int i = blockIdx.x * blockDim.x + threadIdx.x;
    if (i < NN) { g_deg[i] = 0.f; g_cnt[i] = 0; }
    if (blockIdx.x == 0) {
        if (threadIdx.x == 0) { g_idx_is32 = 0; g_mask_is8 = 0; }
        __syncthreads();
        int any_odd = 0, any_off = 0;
        for (int k = 0; k < 64; k++) {
            int s = threadIdx.x + k * blockDim.x;   // s in [0, 16384)
            int w = ei32[2 * s + 1];                // odd word, < 2*EE
            any_odd |= (w != 0);
            unsigned char b = m8[s];                // < EE bytes
            if (s & 3) any_off |= (b != 0);
        }
        if (__syncthreads_or(any_odd)) { if (threadIdx.x == 0) g_idx_is32 = 1; }
        if (__syncthreads_or(any_off)) { if (threadIdx.x == 0) g_mask_is8 = 1; }
    }
}

// decode per dtype flags; w = attr*mask; accumulate deg and cnt at target col
__global__ void k_prep(const float* __restrict__ attr,
                       const int* __restrict__ ei32,
                       const unsigned char* __restrict__ m8) {
    int e = blockIdx.x * blockDim.x + threadIdx.x;
    if (e >= EE) return;
    bool mk = g_mask_is8 ? (m8[e] != 0)
                         : (reinterpret_cast<const int*>(m8)[e] != 0);
    int r, c;
    if (g_idx_is32) { r = ei32[e];        c = ei32[EE + e]; }
    else            { r = ei32[2LL * e];  c = ei32[2LL * (EE + e)]; }
    float w = mk ? __ldg(attr + e) : 0.f;
    if ((unsigned)r >= NN || (unsigned)c >= NN) w = 0.f;
    g_w[e] = w;
    g_row0[e] = r;
    g_col0[e] = c;
    if (w > 0.f) {
        atomicAdd(&g_deg[c], w);
        atomicAdd(&g_cnt[c], 1);
    }
}

// dinv (elementwise) + block-level exclusive scan of cnt
__global__ void k_scan1() {
    __shared__ int sm[SCAN_B];
    int i = blockIdx.x * SCAN_B + threadIdx.x;
    if (i < NN) {
        float d = g_deg[i];
        g_dinv[i] = (d > 0.f) ? rsqrtf(d) : 0.f;
    }
    int v = (i < NN) ? g_cnt[i] : 0;
    sm[threadIdx.x] = v;
    __syncthreads();
    for (int d = 1; d < SCAN_B; d <<= 1) {
        int t = (threadIdx.x >= d) ? sm[threadIdx.x - d] : 0;
        __syncthreads();
        sm[threadIdx.x] += t;
        __syncthreads();
    }
    if (i < NN) g_off[i] = sm[threadIdx.x] - v;  // exclusive within block
    if (threadIdx.x == SCAN_B - 1) g_bsum[blockIdx.x] = sm[SCAN_B - 1];
}

// scan the 98 block sums with one 128-thread block
__global__ void k_scan2() {
    __shared__ int sm[128];
    int v = (threadIdx.x < NBLK) ? g_bsum[threadIdx.x] : 0;
    sm[threadIdx.x] = v;
    __syncthreads();
    for (int d = 1; d < 128; d <<= 1) {
        int t = (threadIdx.x >= d) ? sm[threadIdx.x - d] : 0;
        __syncthreads();
        sm[threadIdx.x] += t;
        __syncthreads();
    }
    if (threadIdx.x < NBLK) g_bsum_off[threadIdx.x] = sm[threadIdx.x] - v;
    if (threadIdx.x == 127) g_off[NN] = sm[127];
}

// add block offsets; init cursors
__global__ void k_scan3() {
    int i = blockIdx.x * blockDim.x + threadIdx.x;
    if (i < NN) {
        int o = g_off[i] + g_bsum_off[i / SCAN_B];
        g_off[i] = o;
        g_cur[i] = o;
    }
}

// fill CSR: (row, norm) pairs grouped by target col (norm may be 0 if
// dinv[row]==0 -- contributes nothing, ~0.25% of edges)
__global__ void k_fill() {
    int e = blockIdx.x * blockDim.x + threadIdx.x;
    if (e >= EE) return;
    float w = g_w[e];
    if (w <= 0.f) return;
    int r = g_row0[e];
    int c = g_col0[e];
    float nrm = w * g_dinv[r] * g_dinv[c];
    int pos = atomicAdd(&g_cur[c], 1);
    g_pair[pos] = make_int2(r, __float_as_int(nrm));
}

// pull one layer: 16 threads/node, register accumulation, unroll x2
__global__ void k_gather(const float* __restrict__ hin, float* __restrict__ hout) {
    int gid = blockIdx.x * blockDim.x + threadIdx.x;
    int node = gid >> 4;
    if (node >= NN) return;
    int lane = gid & 15;
    int j = g_off[node];
    int end = g_off[node + 1];
    float4 acc = make_float4(0.f, 0.f, 0.f, 0.f);
    for (; j + 1 < end; j += 2) {
        int2 p0 = __ldg(&g_pair[j]);
        int2 p1 = __ldg(&g_pair[j + 1]);
        float4 v0 = __ldg(reinterpret_cast<const float4*>(hin + (size_t)p0.x * DD) + lane);
        float4 v1 = __ldg(reinterpret_cast<const float4*>(hin + (size_t)p1.x * DD) + lane);
        float n0 = __int_as_float(p0.y), n1 = __int_as_float(p1.y);
        acc.x = fmaf(n0, v0.x, acc.x); acc.y = fmaf(n0, v0.y, acc.y);
        acc.z = fmaf(n0, v0.z, acc.z); acc.w = fmaf(n0, v0.w, acc.w);
        acc.x = fmaf(n1, v1.x, acc.x); acc.y = fmaf(n1, v1.y, acc.y);
        acc.z = fmaf(n1, v1.z, acc.z); acc.w = fmaf(n1, v1.w, acc.w);
    }
    if (j < end) {
        int2 p0 = __ldg(&g_pair[j]);
        float4 v0 = __ldg(reinterpret_cast<const float4*>(hin + (size_t)p0.x * DD) + lane);
        float n0 = __int_as_float(p0.y);
        acc.x = fmaf(n0, v0.x, acc.x); acc.y = fmaf(n0, v0.y, acc.y);
        acc.z = fmaf(n0, v0.z, acc.z); acc.w = fmaf(n0, v0.w, acc.w);
    }
    reinterpret_cast<float4*>(hout + (size_t)node * DD)[lane] = acc;
}

// last layer fused with epilogue: out = AL*(x + h1 + h2 + acc), h2 == hin
__global__ void k_gather_last(const float* __restrict__ hin,
                              const float* __restrict__ x,
                              const float* __restrict__ h1,
                              float* __restrict__ out) {
    int gid = blockIdx.x * blockDim.x + threadIdx.x;
    int node = gid >> 4;
    if (node >= NN) return;
    int lane = gid & 15;
    int j = g_off[node];
    int end = g_off[node + 1];
    float4 acc = make_float4(0.f, 0.f, 0.f, 0.f);
    for (; j + 1 < end; j += 2) {
        int2 p0 = __ldg(&g_pair[j]);
        int2 p1 = __ldg(&g_pair[j + 1]);
        float4 v0 = __ldg(reinterpret_cast<const float4*>(hin + (size_t)p0.x * DD) + lane);
        float4 v1 = __ldg(reinterpret_cast<const float4*>(hin + (size_t)p1.x * DD) + lane);
        float n0 = __int_as_float(p0.y), n1 = __int_as_float(p1.y);
        acc.x = fmaf(n0, v0.x, acc.x); acc.y = fmaf(n0, v0.y, acc.y);
        acc.z = fmaf(n0, v0.z, acc.z); acc.w = fmaf(n0, v0.w, acc.w);
        acc.x = fmaf(n1, v1.x, acc.x); acc.y = fmaf(n1, v1.y, acc.y);
        acc.z = fmaf(n1, v1.z, acc.z); acc.w = fmaf(n1, v1.w, acc.w);
    }
    if (j < end) {
        int2 p0 = __ldg(&g_pair[j]);
        float4 v0 = __ldg(reinterpret_cast<const float4*>(hin + (size_t)p0.x * DD) + lane);
        float n0 = __int_as_float(p0.y);
        acc.x = fmaf(n0, v0.x, acc.x); acc.y = fmaf(n0, v0.y, acc.y);
        acc.z = fmaf(n0, v0.z, acc.z); acc.w = fmaf(n0, v0.w, acc.w);
    }
    size_t base = (size_t)node * DD;
    float4 a = __ldg(reinterpret_cast<const float4*>(x + base) + lane);
    float4 b = __ldg(reinterpret_cast<const float4*>(h1 + base) + lane);
    float4 c = __ldg(reinterpret_cast<const float4*>(hin + base) + lane);
    float4 o;
    o.x = AL * (a.x + b.x + c.x + acc.x);
    o.y = AL * (a.y + b.y + c.y + acc.y);
    o.z = AL * (a.z + b.z + c.z + acc.z);
    o.w = AL * (a.w + b.w + c.w + acc.w);
    reinterpret_cast<float4*>(out + base)[lane] = o;
}

// ---------------- launch ----------------
extern "C" void kernel_launch(void* const* d_in, const int* in_sizes, int n_in,
                              void* d_out, int out_size) {
    const float* x = (const float*)d_in[0];
    const float* attr = (const float*)d_in[1];
    const int* ei32 = (const int*)d_in[2];
    const unsigned char* m8 = (const unsigned char*)d_in[3];
    float* out = (float*)d_out;

    void* hbp = nullptr;
    cudaGetSymbolAddress(&hbp, g_hbuf);
    float* h1 = (float*)hbp;
    float* h2 = h1 + (size_t)NN * DD;

    const int B = 256;
    const int gridE = (EE + B - 1) / B;
    const int gridN = (NN + B - 1) / B;
    const int gridGather = (NN * 16 + B - 1) / B;

    k_zero_probe<<<gridN, B>>>(ei32, m8);
    k_prep<<<gridE, B>>>(attr, ei32, m8);
    k_scan1<<<NBLK, SCAN_B>>>();
    k_scan2<<<1, 128>>>();
    k_scan3<<<gridN, B>>>();
    k_fill<<<gridE, B>>>();

    k_gather<<<gridGather, B>>>(x,  h1);
    k_gather<<<gridGather, B>>>(h1, h2);
    k_gather_last<<<gridGather, B>>>(h2, x, h1, out);
}